// round 2
// baseline (speedup 1.0000x reference)
#include <cuda_runtime.h>
#include <cuda_bf16.h>

// PointMatcher: pred (N=1024,20,2) vs gt (M=2048,20,2)
// dist(i,j) = mean_p ||pred[i,p]-gt[j,p]||_2 ; argmin over j per i.
// Outputs concatenated in d_out (float32):
//   [0 .. N*40)    matched_points = gt[argmin]
//   [N*40 .. N*41) confidence
//   [N*41 .. N*42) matched_indices (as float)

#define BI      4      // pred rows per block
#define TJ      128    // gt rows per shared tile
#define HJ      64     // j-lanes per block (2 gt rows each per tile)
#define GTC     1024   // gt rows per block (chunk)
#define P       20
#define ROWF    40     // floats per row
#define ROWP    44     // padded shared stride (16B-aligned rows, conflict-free reads)
#define THREADS 256
#define NMAX    1024

__device__ unsigned long long g_best[NMAX];

__device__ __forceinline__ float fsqrt_approx(float x) {
    float r;
    asm("sqrt.approx.f32 %0, %1;" : "=f"(r) : "f"(x));
    return r;
}

__global__ void init_kernel() {
    g_best[blockIdx.x * blockDim.x + threadIdx.x] = ~0ull;
}

__global__ __launch_bounds__(THREADS, 4)
void pm_main_kernel(const float* __restrict__ pred,
                    const float* __restrict__ gt)
{
    __shared__ float tile[TJ * ROWP];            // holds NEGATED gt rows
    __shared__ unsigned long long best[BI];

    const int tid   = threadIdx.x;
    const int il    = tid & (BI - 1);
    const int jlane = tid >> 2;                  // 0..63
    const int i     = blockIdx.y * BI + il;
    const int jbase = blockIdx.x * GTC;

    if (tid < BI) best[tid] = ~0ull;             // visible after first sync in loop

    // pred row: 20 points, each packed {x,y} as one 64-bit f32x2 operand
    unsigned long long pr[P];
    {
        const unsigned long long* p8 =
            (const unsigned long long*)(pred + (size_t)i * ROWF);
        #pragma unroll
        for (int p = 0; p < P; p++) pr[p] = p8[p];
    }

    float minv = 3.402823466e+38f;               // min of SUM (mean deferred)
    int   minj = 0;

    for (int jt = jbase; jt < jbase + GTC; jt += TJ) {
        __syncthreads();
        // Tile load: 1280 float4s, 5 per thread, negated into shared.
        const float4* src = (const float4*)(gt + (size_t)jt * ROWF);
        #pragma unroll
        for (int it = 0; it < 5; it++) {
            int f   = tid + it * THREADS;        // float4 index 0..1279
            int row = f / 10;                    // 10 float4s per row
            int k4  = f - row * 10;
            float4 v = src[f];
            v.x = -v.x; v.y = -v.y; v.z = -v.z; v.w = -v.w;
            *(float4*)(tile + row * ROWP + k4 * 4) = v;
        }
        __syncthreads();

        const unsigned long long* t0 =
            (const unsigned long long*)(tile + jlane * ROWP);
        const unsigned long long* t1 =
            (const unsigned long long*)(tile + (jlane + HJ) * ROWP);
        float sum0 = 0.f, sum1 = 0.f;
        #pragma unroll
        for (int p = 0; p < P; p++) {
            unsigned long long d0, d1;
            // packed {dx,dy} = pred + (-gt)
            asm("add.rn.f32x2 %0, %1, %2;" : "=l"(d0) : "l"(pr[p]), "l"(t0[p]));
            asm("add.rn.f32x2 %0, %1, %2;" : "=l"(d1) : "l"(pr[p]), "l"(t1[p]));
            float dx0, dy0, dx1, dy1;
            asm("mov.b64 {%0,%1}, %2;" : "=f"(dx0), "=f"(dy0) : "l"(d0));
            asm("mov.b64 {%0,%1}, %2;" : "=f"(dx1), "=f"(dy1) : "l"(d1));
            sum0 += fsqrt_approx(fmaf(dx0, dx0, dy0 * dy0));
            sum1 += fsqrt_approx(fmaf(dx1, dx1, dy1 * dy1));
        }
        int j0 = jt + jlane;
        int j1 = jt + jlane + HJ;
        if (sum0 < minv) { minv = sum0; minj = j0; }   // ascending j per thread:
        if (sum1 < minv) { minv = sum1; minj = j1; }   // '<' keeps first tie
    }

    // Block-local argmin, then merge into global scratch.
    unsigned long long key =
        ((unsigned long long)__float_as_uint(minv) << 32) | (unsigned int)minj;
    atomicMin(&best[il], key);
    __syncthreads();
    if (tid < BI)
        atomicMin(&g_best[blockIdx.y * BI + tid], best[tid]);
}

__global__ void pm_finalize_kernel(const float* __restrict__ gt,
                                   float* __restrict__ out, int N)
{
    int t = blockIdx.x * blockDim.x + threadIdx.x;
    int nmp = N * ROWF;
    if (t < nmp) {
        int i = t / ROWF;
        int k = t - i * ROWF;
        int j = (int)(unsigned int)g_best[i];
        out[t] = gt[(size_t)j * ROWF + k];
    } else if (t < nmp + N) {
        int i = t - nmp;
        unsigned long long b = g_best[i];
        float md = __uint_as_float((unsigned int)(b >> 32)) * (1.0f / (float)P);
        out[t] = (md > 2.0f) ? 0.0f : expf(-md);
    } else if (t < nmp + 2 * N) {
        int i = t - nmp - N;
        out[t] = (float)(unsigned int)g_best[i];
    }
}

extern "C" void kernel_launch(void* const* d_in, const int* in_sizes, int n_in,
                              void* d_out, int out_size)
{
    const float* pred = (const float*)d_in[0];
    const float* gt   = (const float*)d_in[1];
    float* out        = (float*)d_out;

    int N = in_sizes[0] / ROWF;   // 1024
    int M = in_sizes[1] / ROWF;   // 2048

    init_kernel<<<N / 256, 256>>>();

    dim3 grid(M / GTC, N / BI);   // (2, 256) = 512 blocks
    pm_main_kernel<<<grid, THREADS>>>(pred, gt);

    int total = N * (ROWF + 2);
    pm_finalize_kernel<<<(total + 255) / 256, 256>>>(gt, out, N);
}

// round 3
// speedup vs baseline: 1.5857x; 1.5857x over previous
#include <cuda_runtime.h>
#include <cuda_bf16.h>

// PointMatcher: pred (N=1024,20,2) vs gt (M=2048,20,2)
// dist(i,j) = mean_p ||pred[i,p]-gt[j,p]||_2 ; argmin over j per i.
// Single kernel. Outputs concatenated in d_out (float32):
//   [0 .. N*40)    matched_points = gt[argmin]
//   [N*40 .. N*41) confidence
//   [N*41 .. N*42) matched_indices (as float)

#define BI      4      // pred rows per block
#define TJ      256    // gt rows per shared tile
#define HJ      128    // j-lanes (each thread: rows jlane and jlane+HJ)
#define P       20
#define ROWF    40     // floats per row
#define ROWP    44     // padded shared stride: rows 12 banks apart -> conflict-free
#define THREADS 512

__device__ __forceinline__ float fsqrt_approx(float x) {
    float r;
    asm("sqrt.approx.f32 %0, %1;" : "=f"(r) : "f"(x));
    return r;
}

__global__ __launch_bounds__(THREADS, 2)
void pointmatcher_kernel(const float* __restrict__ pred,
                         const float* __restrict__ gt,
                         float* __restrict__ out_mp,
                         float* __restrict__ out_conf,
                         float* __restrict__ out_idx,
                         int N, int M)
{
    __shared__ float tile[TJ * ROWP];
    __shared__ unsigned long long best[BI];

    const int tid   = threadIdx.x;
    const int il    = tid & (BI - 1);    // pred row within block
    const int jlane = tid >> 2;          // 0..127
    const int i     = blockIdx.x * BI + il;

    if (tid < BI) best[tid] = ~0ull;     // visible after first sync in loop

    // NEGATED pred row in registers, packed {x,y} per point as f32x2.
    unsigned long long pr[P];
    {
        const float2* p2 = (const float2*)(pred + (size_t)i * ROWF);
        #pragma unroll
        for (int p = 0; p < P; p++) {
            float2 v = p2[p];
            asm("mov.b64 %0, {%1,%2};" : "=l"(pr[p]) : "f"(-v.x), "f"(-v.y));
        }
    }

    float minv = 3.402823466e+38f;       // min of SUM over P (mean deferred)
    int   minj = 0;

    for (int jt = 0; jt < M; jt += TJ) {
        __syncthreads();
        // Tile load: TJ*ROWF = 10240 floats = 2560 float4, 5 per thread.
        const float4* src = (const float4*)(gt + (size_t)jt * ROWF);
        #pragma unroll
        for (int it = 0; it < 5; it++) {
            int f   = tid + it * THREADS;   // float4 index 0..2559
            int row = f / 10;               // 10 float4 per gt row
            int k4  = f - row * 10;
            *(float4*)(tile + row * ROWP + k4 * 4) = src[f];
        }
        __syncthreads();

        const unsigned long long* t0 =
            (const unsigned long long*)(tile + jlane * ROWP);
        const unsigned long long* t1 =
            (const unsigned long long*)(tile + (jlane + HJ) * ROWP);
        float sum0 = 0.f, sum1 = 0.f;
        #pragma unroll
        for (int p = 0; p < P; p++) {
            unsigned long long d0, d1;
            // packed {dx,dy} = gt + (-pred)
            asm("add.rn.f32x2 %0, %1, %2;" : "=l"(d0) : "l"(t0[p]), "l"(pr[p]));
            asm("add.rn.f32x2 %0, %1, %2;" : "=l"(d1) : "l"(t1[p]), "l"(pr[p]));
            float dx0, dy0, dx1, dy1;
            asm("mov.b64 {%0,%1}, %2;" : "=f"(dx0), "=f"(dy0) : "l"(d0));
            asm("mov.b64 {%0,%1}, %2;" : "=f"(dx1), "=f"(dy1) : "l"(d1));
            sum0 += fsqrt_approx(fmaf(dx0, dx0, dy0 * dy0));
            sum1 += fsqrt_approx(fmaf(dx1, dx1, dy1 * dy1));
        }
        int j0 = jt + jlane;
        int j1 = jt + jlane + HJ;
        if (sum0 < minv) { minv = sum0; minj = j0; }  // ascending j per thread:
        if (sum1 < minv) { minv = sum1; minj = j1; }  // '<' keeps first tie
    }

    // Block argmin: packed (dist_bits, j) -> min == (min dist, then min j).
    unsigned long long key =
        ((unsigned long long)__float_as_uint(minv) << 32) | (unsigned int)minj;
    atomicMin(&best[il], key);
    __syncthreads();

    if (tid < BI) {
        unsigned long long b = best[tid];
        int j = (int)(unsigned int)b;
        float md = __uint_as_float((unsigned int)(b >> 32)) * (1.0f / (float)P);
        int row  = blockIdx.x * BI + tid;
        out_conf[row] = (md > 2.0f) ? 0.0f : expf(-md);
        out_idx[row]  = (float)j;
    }
    if (tid < BI * ROWF) {
        int ilg = tid / ROWF;
        int k   = tid - ilg * ROWF;
        int j   = (int)(unsigned int)best[ilg];
        out_mp[(blockIdx.x * BI + ilg) * ROWF + k] = gt[(size_t)j * ROWF + k];
    }
}

extern "C" void kernel_launch(void* const* d_in, const int* in_sizes, int n_in,
                              void* d_out, int out_size)
{
    const float* pred = (const float*)d_in[0];
    const float* gt   = (const float*)d_in[1];
    float* out        = (float*)d_out;

    int N = in_sizes[0] / ROWF;   // 1024
    int M = in_sizes[1] / ROWF;   // 2048

    float* out_mp   = out;
    float* out_conf = out + (size_t)N * ROWF;
    float* out_idx  = out + (size_t)N * ROWF + N;

    pointmatcher_kernel<<<N / BI, THREADS>>>(pred, gt, out_mp, out_conf, out_idx, N, M);
}